// round 3
// baseline (speedup 1.0000x reference)
#include <cuda_runtime.h>

// Problem constants (fixed by the reference)
#define N_NODES 50000
#define N_REL   1000
#define D       128
#define NNZ_MAX 800000

// Scratch (allocation-free rule: __device__ globals)
__device__ float g_exp_lr[N_REL];
__device__ float g_coef[N_REL];        // exp_lr / S
__device__ float g_S;
__device__ int   g_cnt[N_NODES];       // per-row edge counts
__device__ int   g_offs[N_NODES + 1];  // CSR offsets
__device__ int   g_cur[N_NODES];       // reorder cursors
__device__ int2  g_edges[NNZ_MAX];     // CSR-ordered (col, rel)

// ---------------------------------------------------------------------------
// K1: per-relation scores -> exp(leaky_relu(score)). Warp per relation.
// Softmax shift-invariance: shift=0 is safe for O(1)-scale inputs.
// ---------------------------------------------------------------------------
__global__ void __launch_bounds__(256)
k_scores(const float* __restrict__ dual,
         const float* __restrict__ w,
         const float* __restrict__ b) {
    const int lane = threadIdx.x & 31;
    const int r    = (blockIdx.x * blockDim.x + threadIdx.x) >> 5;

    if (blockIdx.x == 0 && threadIdx.x == 0) g_S = 0.f;
    if (r >= N_REL) return;

    const float4 a  = reinterpret_cast<const float4*>(dual + (size_t)r * D)[lane];
    const float4 ww = reinterpret_cast<const float4*>(w)[lane];
    float s = a.x * ww.x + a.y * ww.y + a.z * ww.z + a.w * ww.w;
#pragma unroll
    for (int o = 16; o > 0; o >>= 1)
        s += __shfl_xor_sync(0xffffffffu, s, o);

    if (lane == 0) {
        s += b[0];
        const float lr = (s > 0.f) ? s : 0.01f * s;
        g_exp_lr[r] = expf(lr);
    }
}

// ---------------------------------------------------------------------------
// K2: fused row-histogram + softmax denominator.
// int4-vectorized stream of rows (3.2MB) and rels (3.2MB).
// ---------------------------------------------------------------------------
__global__ void __launch_bounds__(256)
k_hist_sum(const int* __restrict__ rowp, const int* __restrict__ relp, int nnz) {
    const int nvec = nnz >> 2;
    const int4* row4 = reinterpret_cast<const int4*>(rowp);
    const int4* rel4 = reinterpret_cast<const int4*>(relp);

    float s = 0.f;
    for (int i = blockIdx.x * blockDim.x + threadIdx.x; i < nvec;
         i += gridDim.x * blockDim.x) {
        const int4 r = __ldg(row4 + i);
        atomicAdd(&g_cnt[r.x], 1);
        atomicAdd(&g_cnt[r.y], 1);
        atomicAdd(&g_cnt[r.z], 1);
        atomicAdd(&g_cnt[r.w], 1);
        const int4 q = __ldg(rel4 + i);
        s += g_exp_lr[q.x] + g_exp_lr[q.y] + g_exp_lr[q.z] + g_exp_lr[q.w];
    }

#pragma unroll
    for (int o = 16; o > 0; o >>= 1)
        s += __shfl_xor_sync(0xffffffffu, s, o);

    __shared__ float sm[8];
    if ((threadIdx.x & 31) == 0) sm[threadIdx.x >> 5] = s;
    __syncthreads();
    if (threadIdx.x < 32) {
        float v = (threadIdx.x < (blockDim.x >> 5)) ? sm[threadIdx.x] : 0.f;
#pragma unroll
        for (int o = 4; o > 0; o >>= 1)
            v += __shfl_xor_sync(0xffffffffu, v, o);
        if (threadIdx.x == 0) atomicAdd(&g_S, v);
    }
}

// ---------------------------------------------------------------------------
// K3: single-block exclusive scan of g_cnt -> g_offs/g_cur, plus coef
// normalization (needs g_S, which is final by stream order).
// ---------------------------------------------------------------------------
__global__ void __launch_bounds__(1024)
k_scan() {
    __shared__ int sm[1024];
    const int T = 1024;
    const int C = (N_NODES + T - 1) / T;          // 49
    const int t = threadIdx.x;
    const int base = t * C;

    int sum = 0;
    for (int j = 0; j < C; j++) {
        const int idx = base + j;
        if (idx < N_NODES) sum += g_cnt[idx];
    }
    sm[t] = sum;
    __syncthreads();

    // Hillis-Steele inclusive scan over 1024 partials
    for (int o = 1; o < T; o <<= 1) {
        int v = (t >= o) ? sm[t - o] : 0;
        __syncthreads();
        sm[t] += v;
        __syncthreads();
    }
    int run = sm[t] - sum;                        // exclusive prefix for this chunk

    for (int j = 0; j < C; j++) {
        const int idx = base + j;
        if (idx < N_NODES) {
            g_offs[idx] = run;
            g_cur[idx]  = run;
            run += g_cnt[idx];
        }
    }
    if (t == T - 1) g_offs[N_NODES] = run;

    // normalize coef table
    const float invS = 1.0f / g_S;
    if (t < N_REL) g_coef[t] = g_exp_lr[t] * invS;
}

// ---------------------------------------------------------------------------
// K4: reorder edges into CSR order. Thread per edge.
// ---------------------------------------------------------------------------
__global__ void __launch_bounds__(256)
k_reorder(const int* __restrict__ rowp, const int* __restrict__ colp,
          const int* __restrict__ relp, int nnz) {
    const int e = blockIdx.x * blockDim.x + threadIdx.x;
    if (e >= nnz) return;
    const int row = __ldg(rowp + e);
    const int pos = atomicAdd(&g_cur[row], 1);
    g_edges[pos] = make_int2(__ldg(colp + e), __ldg(relp + e));
}

// ---------------------------------------------------------------------------
// K5: gather SpMM. One warp per output row; lane d owns float4 chunk d.
// Register accumulation, single coalesced store. No atomics, no memset.
// ---------------------------------------------------------------------------
__global__ void __launch_bounds__(256)
k_gather(const float* __restrict__ inlayer, float* __restrict__ out) {
    const int lane = threadIdx.x & 31;
    const int row  = (blockIdx.x * blockDim.x + threadIdx.x) >> 5;
    if (row >= N_NODES) return;

    const int s = __ldg(&g_offs[row]);
    const int e = __ldg(&g_offs[row + 1]);

    float4 acc0 = make_float4(0.f, 0.f, 0.f, 0.f);
    float4 acc1 = make_float4(0.f, 0.f, 0.f, 0.f);

    int i = s;
    for (; i + 1 < e; i += 2) {
        const int2 e0 = __ldg(&g_edges[i]);
        const int2 e1 = __ldg(&g_edges[i + 1]);
        const float c0 = g_coef[e0.y];
        const float c1 = g_coef[e1.y];
        const float4 v0 = __ldg(reinterpret_cast<const float4*>(
                                    inlayer + (size_t)e0.x * D) + lane);
        const float4 v1 = __ldg(reinterpret_cast<const float4*>(
                                    inlayer + (size_t)e1.x * D) + lane);
        acc0.x += c0 * v0.x; acc0.y += c0 * v0.y;
        acc0.z += c0 * v0.z; acc0.w += c0 * v0.w;
        acc1.x += c1 * v1.x; acc1.y += c1 * v1.y;
        acc1.z += c1 * v1.z; acc1.w += c1 * v1.w;
    }
    if (i < e) {
        const int2 e0 = __ldg(&g_edges[i]);
        const float c0 = g_coef[e0.y];
        const float4 v0 = __ldg(reinterpret_cast<const float4*>(
                                    inlayer + (size_t)e0.x * D) + lane);
        acc0.x += c0 * v0.x; acc0.y += c0 * v0.y;
        acc0.z += c0 * v0.z; acc0.w += c0 * v0.w;
    }

    acc0.x += acc1.x; acc0.y += acc1.y; acc0.z += acc1.z; acc0.w += acc1.w;
    reinterpret_cast<float4*>(out + (size_t)row * D)[lane] = acc0;
}

// ---------------------------------------------------------------------------
// kernel_launch
// Inputs: 0 inlayer [N,D] f32 | 1 dual [R,D] f32 | 2 conv_w [D] f32
//         3 conv_b [1] f32    | 4 edge_idx [2,NNZ] i32 | 5 edge_rel [NNZ] i32
// Output: [N, D] f32
// ---------------------------------------------------------------------------
extern "C" void kernel_launch(void* const* d_in, const int* in_sizes, int n_in,
                              void* d_out, int out_size) {
    const float* inlayer = (const float*)d_in[0];
    const float* dual    = (const float*)d_in[1];
    const float* conv_w  = (const float*)d_in[2];
    const float* conv_b  = (const float*)d_in[3];
    const int*   eidx    = (const int*)d_in[4];
    const int*   erel    = (const int*)d_in[5];
    float*       out     = (float*)d_out;

    const int nnz = in_sizes[5];
    const int* rowp = eidx;
    const int* colp = eidx + nnz;

    // Zero per-row counters (captured as a memset node; no allocation).
    void* cnt_ptr = nullptr;
    cudaGetSymbolAddress(&cnt_ptr, g_cnt);
    cudaMemsetAsync(cnt_ptr, 0, N_NODES * sizeof(int));

    k_scores<<<(N_REL * 32 + 255) / 256, 256>>>(dual, conv_w, conv_b);
    k_hist_sum<<<592, 256>>>(rowp, erel, nnz);
    k_scan<<<1, 1024>>>();
    k_reorder<<<(nnz + 255) / 256, 256>>>(rowp, colp, erel, nnz);
    k_gather<<<(N_NODES * 32 + 255) / 256, 256>>>(inlayer, out);
}

// round 4
// speedup vs baseline: 2.0235x; 2.0235x over previous
#include <cuda_runtime.h>

#define N_NODES 50000
#define N_REL   1000
#define D       128
#define NNZ_MAX 800000

#define SCAN_BLK 512
#define SCAN_NB  ((N_NODES + SCAN_BLK - 1) / SCAN_BLK)   // 98

// Scratch (allocation-free rule: __device__ globals)
__device__ float g_exp_lr[N_REL];
__device__ float g_coef[N_REL];
__device__ float g_S;
__device__ int   g_cnt[N_NODES];
__device__ int   g_incl[N_NODES];       // block-local inclusive scan
__device__ int   g_bsum[SCAN_NB];       // per-block totals
__device__ int   g_bpre[SCAN_NB];       // exclusive prefix of totals
__device__ int   g_offs[N_NODES + 1];
__device__ int   g_cur[N_NODES];
__device__ int2  g_edges[NNZ_MAX];      // CSR-ordered (col, rel)

// ---------------------------------------------------------------------------
// K1: relation scores -> exp(leaky_relu). Warp per relation. shift=0 is safe.
// ---------------------------------------------------------------------------
__global__ void __launch_bounds__(256)
k_scores(const float* __restrict__ dual, const float* __restrict__ w,
         const float* __restrict__ b) {
    const int lane = threadIdx.x & 31;
    const int r    = (blockIdx.x * blockDim.x + threadIdx.x) >> 5;
    if (blockIdx.x == 0 && threadIdx.x == 0) g_S = 0.f;
    if (r >= N_REL) return;

    const float4 a  = reinterpret_cast<const float4*>(dual + (size_t)r * D)[lane];
    const float4 ww = reinterpret_cast<const float4*>(w)[lane];
    float s = a.x * ww.x + a.y * ww.y + a.z * ww.z + a.w * ww.w;
#pragma unroll
    for (int o = 16; o > 0; o >>= 1) s += __shfl_xor_sync(0xffffffffu, s, o);
    if (lane == 0) {
        s += b[0];
        const float lr = (s > 0.f) ? s : 0.01f * s;
        g_exp_lr[r] = expf(lr);
    }
}

// ---------------------------------------------------------------------------
// K2: fused row-histogram + softmax denominator, 2x int4 ILP per thread.
// ---------------------------------------------------------------------------
__global__ void __launch_bounds__(256)
k_hist_sum(const int* __restrict__ rowp, const int* __restrict__ relp, int nnz) {
    const int nvec = nnz >> 2;            // 200000 int4s
    const int4* row4 = reinterpret_cast<const int4*>(rowp);
    const int4* rel4 = reinterpret_cast<const int4*>(relp);

    float s = 0.f;
    const int stride = gridDim.x * blockDim.x;
    int i = blockIdx.x * blockDim.x + threadIdx.x;
    for (; i + stride < nvec; i += 2 * stride) {
        const int4 r0 = __ldg(row4 + i);
        const int4 r1 = __ldg(row4 + i + stride);
        const int4 q0 = __ldg(rel4 + i);
        const int4 q1 = __ldg(rel4 + i + stride);
        atomicAdd(&g_cnt[r0.x], 1); atomicAdd(&g_cnt[r0.y], 1);
        atomicAdd(&g_cnt[r0.z], 1); atomicAdd(&g_cnt[r0.w], 1);
        atomicAdd(&g_cnt[r1.x], 1); atomicAdd(&g_cnt[r1.y], 1);
        atomicAdd(&g_cnt[r1.z], 1); atomicAdd(&g_cnt[r1.w], 1);
        s += g_exp_lr[q0.x] + g_exp_lr[q0.y] + g_exp_lr[q0.z] + g_exp_lr[q0.w];
        s += g_exp_lr[q1.x] + g_exp_lr[q1.y] + g_exp_lr[q1.z] + g_exp_lr[q1.w];
    }
    for (; i < nvec; i += stride) {
        const int4 r0 = __ldg(row4 + i);
        const int4 q0 = __ldg(rel4 + i);
        atomicAdd(&g_cnt[r0.x], 1); atomicAdd(&g_cnt[r0.y], 1);
        atomicAdd(&g_cnt[r0.z], 1); atomicAdd(&g_cnt[r0.w], 1);
        s += g_exp_lr[q0.x] + g_exp_lr[q0.y] + g_exp_lr[q0.z] + g_exp_lr[q0.w];
    }

#pragma unroll
    for (int o = 16; o > 0; o >>= 1) s += __shfl_xor_sync(0xffffffffu, s, o);
    __shared__ float sm[8];
    if ((threadIdx.x & 31) == 0) sm[threadIdx.x >> 5] = s;
    __syncthreads();
    if (threadIdx.x < 32) {
        float v = (threadIdx.x < (blockDim.x >> 5)) ? sm[threadIdx.x] : 0.f;
#pragma unroll
        for (int o = 4; o > 0; o >>= 1) v += __shfl_xor_sync(0xffffffffu, v, o);
        if (threadIdx.x == 0) atomicAdd(&g_S, v);
    }
}

// ---------------------------------------------------------------------------
// K3a: block-level inclusive scan of g_cnt (512/block), write block totals.
// ---------------------------------------------------------------------------
__global__ void __launch_bounds__(SCAN_BLK)
k_scan1() {
    __shared__ int sm[SCAN_BLK];
    const int gid = blockIdx.x * SCAN_BLK + threadIdx.x;
    int v = (gid < N_NODES) ? g_cnt[gid] : 0;
    sm[threadIdx.x] = v;
    __syncthreads();
#pragma unroll
    for (int o = 1; o < SCAN_BLK; o <<= 1) {
        int p = (threadIdx.x >= o) ? sm[threadIdx.x - o] : 0;
        __syncthreads();
        sm[threadIdx.x] += p;
        __syncthreads();
    }
    if (gid < N_NODES) g_incl[gid] = sm[threadIdx.x];
    if (threadIdx.x == SCAN_BLK - 1) g_bsum[blockIdx.x] = sm[threadIdx.x];
}

// ---------------------------------------------------------------------------
// K3b: scan the 98 block totals (1 block); also normalize coef table and
// write g_offs[N] = nnz.
// ---------------------------------------------------------------------------
__global__ void __launch_bounds__(1024)
k_scan2(int nnz) {
    __shared__ int sm[SCAN_NB];
    const int t = threadIdx.x;
    if (t < SCAN_NB) sm[t] = g_bsum[t];
    __syncthreads();
    if (t == 0) {
        int run = 0;
        for (int i = 0; i < SCAN_NB; i++) { g_bpre[i] = run; run += sm[i]; }
        g_offs[N_NODES] = nnz;
    }
    const float invS = 1.0f / g_S;
    if (t < N_REL) g_coef[t] = g_exp_lr[t] * invS;
}

// ---------------------------------------------------------------------------
// K3c: final offsets: exclusive = bpre[blk] + incl - cnt. Also init cursors.
// ---------------------------------------------------------------------------
__global__ void __launch_bounds__(SCAN_BLK)
k_scan3() {
    const int gid = blockIdx.x * SCAN_BLK + threadIdx.x;
    if (gid >= N_NODES) return;
    const int off = g_bpre[blockIdx.x] + g_incl[gid] - g_cnt[gid];
    g_offs[gid] = off;
    g_cur[gid]  = off;
}

// ---------------------------------------------------------------------------
// K4: reorder into CSR order, 4 edges per thread (int4 loads, 4 independent
// atomics overlapped).
// ---------------------------------------------------------------------------
__global__ void __launch_bounds__(256)
k_reorder(const int* __restrict__ rowp, const int* __restrict__ colp,
          const int* __restrict__ relp, int nnz) {
    const int nvec = nnz >> 2;
    const int i = blockIdx.x * blockDim.x + threadIdx.x;
    if (i < nvec) {
        const int4 r = __ldg(reinterpret_cast<const int4*>(rowp) + i);
        const int4 c = __ldg(reinterpret_cast<const int4*>(colp) + i);
        const int4 q = __ldg(reinterpret_cast<const int4*>(relp) + i);
        const int p0 = atomicAdd(&g_cur[r.x], 1);
        const int p1 = atomicAdd(&g_cur[r.y], 1);
        const int p2 = atomicAdd(&g_cur[r.z], 1);
        const int p3 = atomicAdd(&g_cur[r.w], 1);
        g_edges[p0] = make_int2(c.x, q.x);
        g_edges[p1] = make_int2(c.y, q.y);
        g_edges[p2] = make_int2(c.z, q.z);
        g_edges[p3] = make_int2(c.w, q.w);
    }
    // tail (nnz not divisible by 4)
    const int e = (nvec << 2) + i;
    if (e < nnz) {
        const int row = __ldg(rowp + e);
        const int pos = atomicAdd(&g_cur[row], 1);
        g_edges[pos] = make_int2(__ldg(colp + e), __ldg(relp + e));
    }
}

// ---------------------------------------------------------------------------
// K5: gather SpMM. Warp per row, 4 independent gathers in flight.
// ---------------------------------------------------------------------------
__global__ void __launch_bounds__(256)
k_gather(const float* __restrict__ inlayer, float* __restrict__ out) {
    const int lane = threadIdx.x & 31;
    const int row  = (blockIdx.x * blockDim.x + threadIdx.x) >> 5;
    if (row >= N_NODES) return;

    const int s = __ldg(&g_offs[row]);
    const int e = __ldg(&g_offs[row + 1]);

    float4 a0 = make_float4(0.f, 0.f, 0.f, 0.f);
    float4 a1 = make_float4(0.f, 0.f, 0.f, 0.f);
    float4 a2 = make_float4(0.f, 0.f, 0.f, 0.f);
    float4 a3 = make_float4(0.f, 0.f, 0.f, 0.f);

    int i = s;
    for (; i + 3 < e; i += 4) {
        const int2 e0 = __ldg(&g_edges[i]);
        const int2 e1 = __ldg(&g_edges[i + 1]);
        const int2 e2 = __ldg(&g_edges[i + 2]);
        const int2 e3 = __ldg(&g_edges[i + 3]);
        const float4 v0 = __ldg(reinterpret_cast<const float4*>(inlayer + (size_t)e0.x * D) + lane);
        const float4 v1 = __ldg(reinterpret_cast<const float4*>(inlayer + (size_t)e1.x * D) + lane);
        const float4 v2 = __ldg(reinterpret_cast<const float4*>(inlayer + (size_t)e2.x * D) + lane);
        const float4 v3 = __ldg(reinterpret_cast<const float4*>(inlayer + (size_t)e3.x * D) + lane);
        const float c0 = g_coef[e0.y], c1 = g_coef[e1.y];
        const float c2 = g_coef[e2.y], c3 = g_coef[e3.y];
        a0.x += c0 * v0.x; a0.y += c0 * v0.y; a0.z += c0 * v0.z; a0.w += c0 * v0.w;
        a1.x += c1 * v1.x; a1.y += c1 * v1.y; a1.z += c1 * v1.z; a1.w += c1 * v1.w;
        a2.x += c2 * v2.x; a2.y += c2 * v2.y; a2.z += c2 * v2.z; a2.w += c2 * v2.w;
        a3.x += c3 * v3.x; a3.y += c3 * v3.y; a3.z += c3 * v3.z; a3.w += c3 * v3.w;
    }
    for (; i < e; i++) {
        const int2 e0 = __ldg(&g_edges[i]);
        const float c0 = g_coef[e0.y];
        const float4 v0 = __ldg(reinterpret_cast<const float4*>(inlayer + (size_t)e0.x * D) + lane);
        a0.x += c0 * v0.x; a0.y += c0 * v0.y; a0.z += c0 * v0.z; a0.w += c0 * v0.w;
    }

    a0.x += a1.x + a2.x + a3.x;
    a0.y += a1.y + a2.y + a3.y;
    a0.z += a1.z + a2.z + a3.z;
    a0.w += a1.w + a2.w + a3.w;
    reinterpret_cast<float4*>(out + (size_t)row * D)[lane] = a0;
}

// ---------------------------------------------------------------------------
// kernel_launch
// Inputs: 0 inlayer [N,D] f32 | 1 dual [R,D] f32 | 2 conv_w [D] f32
//         3 conv_b [1] f32    | 4 edge_idx [2,NNZ] i32 | 5 edge_rel [NNZ] i32
// Output: [N, D] f32
// ---------------------------------------------------------------------------
extern "C" void kernel_launch(void* const* d_in, const int* in_sizes, int n_in,
                              void* d_out, int out_size) {
    const float* inlayer = (const float*)d_in[0];
    const float* dual    = (const float*)d_in[1];
    const float* conv_w  = (const float*)d_in[2];
    const float* conv_b  = (const float*)d_in[3];
    const int*   eidx    = (const int*)d_in[4];
    const int*   erel    = (const int*)d_in[5];
    float*       out     = (float*)d_out;

    const int nnz = in_sizes[5];
    const int* rowp = eidx;
    const int* colp = eidx + nnz;

    void* cnt_ptr = nullptr;
    cudaGetSymbolAddress(&cnt_ptr, g_cnt);
    cudaMemsetAsync(cnt_ptr, 0, N_NODES * sizeof(int));

    k_scores<<<(N_REL * 32 + 255) / 256, 256>>>(dual, conv_w, conv_b);
    k_hist_sum<<<296, 256>>>(rowp, erel, nnz);
    k_scan1<<<SCAN_NB, SCAN_BLK>>>();
    k_scan2<<<1, 1024>>>(nnz);
    k_scan3<<<SCAN_NB, SCAN_BLK>>>();
    k_reorder<<<(nnz / 4 + 255) / 256, 256>>>(rowp, colp, erel, nnz);
    k_gather<<<(N_NODES * 32 + 255) / 256, 256>>>(inlayer, out);
}

// round 5
// speedup vs baseline: 2.0245x; 1.0005x over previous
#include <cuda_runtime.h>

#define N_NODES 50000
#define N_REL   1000
#define D       128
#define NNZ_MAX 800000

#define SCAN_BLK 512
#define SCAN_NB  ((N_NODES + SCAN_BLK - 1) / SCAN_BLK)   // 98

// Scratch (allocation-free rule: __device__ globals)
__device__ float g_exp_lr[N_REL];
__device__ float g_coef[N_REL];
__device__ float g_S;
__device__ int   g_cnt[N_NODES];
__device__ int   g_incl[N_NODES];
__device__ int   g_bsum[SCAN_NB];
__device__ int   g_bpre[SCAN_NB];
__device__ int   g_offs[N_NODES + 1];
__device__ int   g_cur[N_NODES];
// Packed CSR edges: bits[0:16) = col, bits[16:26) = rel. 16B-aligned for uint4.
__device__ __align__(16) unsigned g_edges[NNZ_MAX];

// ---------------------------------------------------------------------------
// K1: relation scores -> exp(leaky_relu). Warp per relation. shift=0 is safe
// (softmax shift-invariance; O(1)-scale inputs).
// ---------------------------------------------------------------------------
__global__ void __launch_bounds__(256)
k_scores(const float* __restrict__ dual, const float* __restrict__ w,
         const float* __restrict__ b) {
    const int lane = threadIdx.x & 31;
    const int r    = (blockIdx.x * blockDim.x + threadIdx.x) >> 5;
    if (blockIdx.x == 0 && threadIdx.x == 0) g_S = 0.f;
    if (r >= N_REL) return;

    const float4 a  = reinterpret_cast<const float4*>(dual + (size_t)r * D)[lane];
    const float4 ww = reinterpret_cast<const float4*>(w)[lane];
    float s = a.x * ww.x + a.y * ww.y + a.z * ww.z + a.w * ww.w;
#pragma unroll
    for (int o = 16; o > 0; o >>= 1) s += __shfl_xor_sync(0xffffffffu, s, o);
    if (lane == 0) {
        s += b[0];
        const float lr = (s > 0.f) ? s : 0.01f * s;
        g_exp_lr[r] = expf(lr);
    }
}

// ---------------------------------------------------------------------------
// K2: fused row-histogram + softmax denominator, 2x int4 ILP.
// ---------------------------------------------------------------------------
__global__ void __launch_bounds__(256)
k_hist_sum(const int* __restrict__ rowp, const int* __restrict__ relp, int nnz) {
    const int nvec = nnz >> 2;
    const int4* row4 = reinterpret_cast<const int4*>(rowp);
    const int4* rel4 = reinterpret_cast<const int4*>(relp);

    float s = 0.f;
    const int stride = gridDim.x * blockDim.x;
    int i = blockIdx.x * blockDim.x + threadIdx.x;
    for (; i + stride < nvec; i += 2 * stride) {
        const int4 r0 = __ldg(row4 + i);
        const int4 r1 = __ldg(row4 + i + stride);
        const int4 q0 = __ldg(rel4 + i);
        const int4 q1 = __ldg(rel4 + i + stride);
        atomicAdd(&g_cnt[r0.x], 1); atomicAdd(&g_cnt[r0.y], 1);
        atomicAdd(&g_cnt[r0.z], 1); atomicAdd(&g_cnt[r0.w], 1);
        atomicAdd(&g_cnt[r1.x], 1); atomicAdd(&g_cnt[r1.y], 1);
        atomicAdd(&g_cnt[r1.z], 1); atomicAdd(&g_cnt[r1.w], 1);
        s += g_exp_lr[q0.x] + g_exp_lr[q0.y] + g_exp_lr[q0.z] + g_exp_lr[q0.w];
        s += g_exp_lr[q1.x] + g_exp_lr[q1.y] + g_exp_lr[q1.z] + g_exp_lr[q1.w];
    }
    for (; i < nvec; i += stride) {
        const int4 r0 = __ldg(row4 + i);
        const int4 q0 = __ldg(rel4 + i);
        atomicAdd(&g_cnt[r0.x], 1); atomicAdd(&g_cnt[r0.y], 1);
        atomicAdd(&g_cnt[r0.z], 1); atomicAdd(&g_cnt[r0.w], 1);
        s += g_exp_lr[q0.x] + g_exp_lr[q0.y] + g_exp_lr[q0.z] + g_exp_lr[q0.w];
    }

#pragma unroll
    for (int o = 16; o > 0; o >>= 1) s += __shfl_xor_sync(0xffffffffu, s, o);
    __shared__ float sm[8];
    if ((threadIdx.x & 31) == 0) sm[threadIdx.x >> 5] = s;
    __syncthreads();
    if (threadIdx.x < 32) {
        float v = (threadIdx.x < (blockDim.x >> 5)) ? sm[threadIdx.x] : 0.f;
#pragma unroll
        for (int o = 4; o > 0; o >>= 1) v += __shfl_xor_sync(0xffffffffu, v, o);
        if (threadIdx.x == 0) atomicAdd(&g_S, v);
    }
}

// ---------------------------------------------------------------------------
// K3a: block-level inclusive scan of g_cnt, write block totals.
// ---------------------------------------------------------------------------
__global__ void __launch_bounds__(SCAN_BLK)
k_scan1() {
    __shared__ int sm[SCAN_BLK];
    const int gid = blockIdx.x * SCAN_BLK + threadIdx.x;
    int v = (gid < N_NODES) ? g_cnt[gid] : 0;
    sm[threadIdx.x] = v;
    __syncthreads();
#pragma unroll
    for (int o = 1; o < SCAN_BLK; o <<= 1) {
        int p = (threadIdx.x >= o) ? sm[threadIdx.x - o] : 0;
        __syncthreads();
        sm[threadIdx.x] += p;
        __syncthreads();
    }
    if (gid < N_NODES) g_incl[gid] = sm[threadIdx.x];
    if (threadIdx.x == SCAN_BLK - 1) g_bsum[blockIdx.x] = sm[threadIdx.x];
}

// ---------------------------------------------------------------------------
// K3b: PARALLEL scan of the 98 block totals (Hillis-Steele, 128 threads),
// plus coef normalization and g_offs[N] = nnz.
// ---------------------------------------------------------------------------
__global__ void __launch_bounds__(1024)
k_scan2(int nnz) {
    __shared__ int sm[128];
    const int t = threadIdx.x;

    if (t < 128) {
        const int v = (t < SCAN_NB) ? g_bsum[t] : 0;
        sm[t] = v;
        __syncthreads();
#pragma unroll
        for (int o = 1; o < 128; o <<= 1) {
            const int p = (t >= o) ? sm[t - o] : 0;
            __syncthreads();
            sm[t] += p;
            __syncthreads();
        }
        if (t < SCAN_NB) g_bpre[t] = sm[t] - v;   // exclusive prefix
        if (t == 0) g_offs[N_NODES] = nnz;
    } else {
        // match the 2*log2(128) barriers executed by the scan threads
#pragma unroll
        for (int o = 1; o < 128; o <<= 1) { __syncthreads(); __syncthreads(); }
    }

    const float invS = 1.0f / g_S;
    if (t < N_REL) g_coef[t] = g_exp_lr[t] * invS;
}

// ---------------------------------------------------------------------------
// K3c: final offsets = bpre[blk] + incl - cnt; init cursors.
// ---------------------------------------------------------------------------
__global__ void __launch_bounds__(SCAN_BLK)
k_scan3() {
    const int gid = blockIdx.x * SCAN_BLK + threadIdx.x;
    if (gid >= N_NODES) return;
    const int off = g_bpre[blockIdx.x] + g_incl[gid] - g_cnt[gid];
    g_offs[gid] = off;
    g_cur[gid]  = off;
}

// ---------------------------------------------------------------------------
// K4: reorder into packed CSR edges, 4 edges per thread.
// ---------------------------------------------------------------------------
__global__ void __launch_bounds__(256)
k_reorder(const int* __restrict__ rowp, const int* __restrict__ colp,
          const int* __restrict__ relp, int nnz) {
    const int nvec = nnz >> 2;
    const int i = blockIdx.x * blockDim.x + threadIdx.x;
    if (i < nvec) {
        const int4 r = __ldg(reinterpret_cast<const int4*>(rowp) + i);
        const int4 c = __ldg(reinterpret_cast<const int4*>(colp) + i);
        const int4 q = __ldg(reinterpret_cast<const int4*>(relp) + i);
        const int p0 = atomicAdd(&g_cur[r.x], 1);
        const int p1 = atomicAdd(&g_cur[r.y], 1);
        const int p2 = atomicAdd(&g_cur[r.z], 1);
        const int p3 = atomicAdd(&g_cur[r.w], 1);
        g_edges[p0] = (unsigned)c.x | ((unsigned)q.x << 16);
        g_edges[p1] = (unsigned)c.y | ((unsigned)q.y << 16);
        g_edges[p2] = (unsigned)c.z | ((unsigned)q.z << 16);
        g_edges[p3] = (unsigned)c.w | ((unsigned)q.w << 16);
    }
    const int e = (nvec << 2) + i;
    if (e < nnz) {
        const int row = __ldg(rowp + e);
        const int pos = atomicAdd(&g_cur[row], 1);
        g_edges[pos] = (unsigned)__ldg(colp + e) | ((unsigned)__ldg(relp + e) << 16);
    }
}

// ---------------------------------------------------------------------------
// K5: gather SpMM. Warp per row; uint4 broadcast edge loads (4 edges/load),
// 4 independent 512B gathers in flight.
// ---------------------------------------------------------------------------
__device__ __forceinline__ void acc_edge(unsigned p, int lane,
                                         const float* __restrict__ inlayer,
                                         float4& a) {
    const int   col = (int)(p & 0xFFFFu);
    const float c   = g_coef[p >> 16];
    const float4 v  = __ldg(reinterpret_cast<const float4*>(
                                inlayer + (size_t)col * D) + lane);
    a.x += c * v.x; a.y += c * v.y; a.z += c * v.z; a.w += c * v.w;
}

__global__ void __launch_bounds__(256)
k_gather(const float* __restrict__ inlayer, float* __restrict__ out) {
    const int lane = threadIdx.x & 31;
    const int row  = (blockIdx.x * blockDim.x + threadIdx.x) >> 5;
    if (row >= N_NODES) return;

    const int s = __ldg(&g_offs[row]);
    const int e = __ldg(&g_offs[row + 1]);

    float4 a0 = make_float4(0.f, 0.f, 0.f, 0.f);
    float4 a1 = make_float4(0.f, 0.f, 0.f, 0.f);
    float4 a2 = make_float4(0.f, 0.f, 0.f, 0.f);
    float4 a3 = make_float4(0.f, 0.f, 0.f, 0.f);

    int i = s;
    // scalar head until 16B-aligned
    while (i < e && (i & 3)) { acc_edge(__ldg(&g_edges[i]), lane, inlayer, a0); i++; }
    // vector body: one broadcast uint4 = 4 edges
    for (; i + 3 < e; i += 4) {
        const uint4 p = __ldg(reinterpret_cast<const uint4*>(g_edges + i));
        acc_edge(p.x, lane, inlayer, a0);
        acc_edge(p.y, lane, inlayer, a1);
        acc_edge(p.z, lane, inlayer, a2);
        acc_edge(p.w, lane, inlayer, a3);
    }
    // scalar tail
    for (; i < e; i++) acc_edge(__ldg(&g_edges[i]), lane, inlayer, a0);

    a0.x += a1.x + a2.x + a3.x;
    a0.y += a1.y + a2.y + a3.y;
    a0.z += a1.z + a2.z + a3.z;
    a0.w += a1.w + a2.w + a3.w;
    reinterpret_cast<float4*>(out + (size_t)row * D)[lane] = a0;
}

// ---------------------------------------------------------------------------
// kernel_launch
// Inputs: 0 inlayer [N,D] f32 | 1 dual [R,D] f32 | 2 conv_w [D] f32
//         3 conv_b [1] f32    | 4 edge_idx [2,NNZ] i32 | 5 edge_rel [NNZ] i32
// Output: [N, D] f32
// ---------------------------------------------------------------------------
extern "C" void kernel_launch(void* const* d_in, const int* in_sizes, int n_in,
                              void* d_out, int out_size) {
    const float* inlayer = (const float*)d_in[0];
    const float* dual    = (const float*)d_in[1];
    const float* conv_w  = (const float*)d_in[2];
    const float* conv_b  = (const float*)d_in[3];
    const int*   eidx    = (const int*)d_in[4];
    const int*   erel    = (const int*)d_in[5];
    float*       out     = (float*)d_out;

    const int nnz = in_sizes[5];
    const int* rowp = eidx;
    const int* colp = eidx + nnz;

    void* cnt_ptr = nullptr;
    cudaGetSymbolAddress(&cnt_ptr, g_cnt);
    cudaMemsetAsync(cnt_ptr, 0, N_NODES * sizeof(int));

    k_scores<<<(N_REL * 32 + 255) / 256, 256>>>(dual, conv_w, conv_b);
    k_hist_sum<<<296, 256>>>(rowp, erel, nnz);
    k_scan1<<<SCAN_NB, SCAN_BLK>>>();
    k_scan2<<<1, 1024>>>(nnz);
    k_scan3<<<SCAN_NB, SCAN_BLK>>>();
    k_reorder<<<(nnz / 4 + 255) / 256, 256>>>(rowp, colp, erel, nnz);
    k_gather<<<(N_NODES * 32 + 255) / 256, 256>>>(inlayer, out);
}

// round 6
// speedup vs baseline: 2.2208x; 1.0970x over previous
#include <cuda_runtime.h>

#define N_NODES 50000
#define N_REL   1000
#define D       128
#define NNZ_MAX 800000

#define SCAN_BLK 512
#define SCAN_NB  ((N_NODES + SCAN_BLK - 1) / SCAN_BLK)   // 98 (< 148 SMs: co-resident)

// Scratch (allocation-free rule: __device__ globals)
__device__ float g_exp_lr[N_REL];
__device__ float g_coef[N_REL];
__device__ float g_S;
__device__ int   g_cnt[N_NODES];
__device__ int   g_bsum[SCAN_NB];
__device__ int   g_done;                 // grid-barrier counter (zeroed in K1)
__device__ int   g_offs[N_NODES + 1];
__device__ int   g_cur[N_NODES];
// Packed CSR edges: bits[0:16) = col, bits[16:26) = rel. 16B-aligned for uint4.
__device__ __align__(16) unsigned g_edges[NNZ_MAX];

// ---------------------------------------------------------------------------
// K1: relation scores -> exp(leaky_relu)  (warp per relation; shift=0 safe),
// FUSED with zeroing of g_cnt / g_S / g_done.
// ---------------------------------------------------------------------------
__global__ void __launch_bounds__(256)
k_scores(const float* __restrict__ dual, const float* __restrict__ w,
         const float* __restrict__ b) {
    const int tid  = blockIdx.x * blockDim.x + threadIdx.x;
    const int lane = threadIdx.x & 31;
    const int r    = tid >> 5;

    // zero counters: 32000 threads cover 50000 ints in 2 strided passes
    for (int i = tid; i < N_NODES; i += gridDim.x * blockDim.x) g_cnt[i] = 0;
    if (tid == 0) { g_S = 0.f; g_done = 0; }

    if (r >= N_REL) return;
    const float4 a  = reinterpret_cast<const float4*>(dual + (size_t)r * D)[lane];
    const float4 ww = reinterpret_cast<const float4*>(w)[lane];
    float s = a.x * ww.x + a.y * ww.y + a.z * ww.z + a.w * ww.w;
#pragma unroll
    for (int o = 16; o > 0; o >>= 1) s += __shfl_xor_sync(0xffffffffu, s, o);
    if (lane == 0) {
        s += b[0];
        const float lr = (s > 0.f) ? s : 0.01f * s;
        g_exp_lr[r] = expf(lr);
    }
}

// ---------------------------------------------------------------------------
// K2: fused row-histogram + softmax denominator (grid-stride, int4).
// ---------------------------------------------------------------------------
__global__ void __launch_bounds__(256)
k_hist_sum(const int* __restrict__ rowp, const int* __restrict__ relp, int nnz) {
    const int nvec = nnz >> 2;
    const int4* row4 = reinterpret_cast<const int4*>(rowp);
    const int4* rel4 = reinterpret_cast<const int4*>(relp);

    float s = 0.f;
    const int stride = gridDim.x * blockDim.x;
    for (int i = blockIdx.x * blockDim.x + threadIdx.x; i < nvec; i += stride) {
        const int4 r0 = __ldg(row4 + i);
        const int4 q0 = __ldg(rel4 + i);
        atomicAdd(&g_cnt[r0.x], 1); atomicAdd(&g_cnt[r0.y], 1);
        atomicAdd(&g_cnt[r0.z], 1); atomicAdd(&g_cnt[r0.w], 1);
        s += g_exp_lr[q0.x] + g_exp_lr[q0.y] + g_exp_lr[q0.z] + g_exp_lr[q0.w];
    }
    // tail edges (nnz % 4)
    const int e0 = (nvec << 2) + blockIdx.x * blockDim.x + threadIdx.x;
    if (e0 < nnz) {
        atomicAdd(&g_cnt[__ldg(rowp + e0)], 1);
        s += g_exp_lr[__ldg(relp + e0)];
    }

#pragma unroll
    for (int o = 16; o > 0; o >>= 1) s += __shfl_xor_sync(0xffffffffu, s, o);
    __shared__ float sm[8];
    if ((threadIdx.x & 31) == 0) sm[threadIdx.x >> 5] = s;
    __syncthreads();
    if (threadIdx.x < 32) {
        float v = (threadIdx.x < (blockDim.x >> 5)) ? sm[threadIdx.x] : 0.f;
#pragma unroll
        for (int o = 4; o > 0; o >>= 1) v += __shfl_xor_sync(0xffffffffu, v, o);
        if (threadIdx.x == 0) atomicAdd(&g_S, v);
    }
}

// ---------------------------------------------------------------------------
// K3: single-kernel scan with software grid barrier.
// 98 blocks x 512 threads, all co-resident (98 < 148 SMs) -> spin is safe.
// Phase 1: block-local inclusive scan; publish block total; arrive.
// Phase 2: spin until all totals published; parallel-reduce predecessors'
//          totals for the block base; write g_offs / g_cur.
// Block 0 also normalizes the coef table (g_S final by stream order).
// ---------------------------------------------------------------------------
__global__ void __launch_bounds__(SCAN_BLK)
k_scan(int nnz) {
    __shared__ int sm[SCAN_BLK];
    const int t   = threadIdx.x;
    const int bid = blockIdx.x;
    const int gid = bid * SCAN_BLK + t;

    // coef normalization (block 0, overlapped with scan work)
    if (bid == 0) {
        const float invS = 1.0f / g_S;
        for (int r = t; r < N_REL; r += SCAN_BLK) g_coef[r] = g_exp_lr[r] * invS;
    }

    const int v = (gid < N_NODES) ? g_cnt[gid] : 0;
    sm[t] = v;
    __syncthreads();
#pragma unroll
    for (int o = 1; o < SCAN_BLK; o <<= 1) {
        const int p = (t >= o) ? sm[t - o] : 0;
        __syncthreads();
        sm[t] += p;
        __syncthreads();
    }
    const int incl = sm[t];

    if (t == SCAN_BLK - 1) {
        g_bsum[bid] = incl;                       // block total
        __threadfence();
        atomicAdd(&g_done, 1);
    }

    // grid barrier: wait until all 98 totals are visible
    if (t == 0) {
        while (atomicAdd(&g_done, 0) < SCAN_NB) {}
    }
    __syncthreads();

    // block base = sum of predecessors' totals (parallel reduce)
    sm[t] = (t < bid) ? g_bsum[t] : 0;
    __syncthreads();
#pragma unroll
    for (int o = SCAN_BLK / 2; o > 0; o >>= 1) {
        if (t < o) sm[t] += sm[t + o];
        __syncthreads();
    }
    const int base = sm[0];

    if (gid < N_NODES) {
        const int off = base + incl - v;          // exclusive prefix
        g_offs[gid] = off;
        g_cur[gid]  = off;
    }
    if (gid == N_NODES - 1) g_offs[N_NODES] = nnz;
}

// ---------------------------------------------------------------------------
// K4: reorder into packed CSR edges, 4 edges per thread (overlapped atomics).
// ---------------------------------------------------------------------------
__global__ void __launch_bounds__(256)
k_reorder(const int* __restrict__ rowp, const int* __restrict__ colp,
          const int* __restrict__ relp, int nnz) {
    const int nvec = nnz >> 2;
    const int i = blockIdx.x * blockDim.x + threadIdx.x;
    if (i < nvec) {
        const int4 r = __ldg(reinterpret_cast<const int4*>(rowp) + i);
        const int4 c = __ldg(reinterpret_cast<const int4*>(colp) + i);
        const int4 q = __ldg(reinterpret_cast<const int4*>(relp) + i);
        const int p0 = atomicAdd(&g_cur[r.x], 1);
        const int p1 = atomicAdd(&g_cur[r.y], 1);
        const int p2 = atomicAdd(&g_cur[r.z], 1);
        const int p3 = atomicAdd(&g_cur[r.w], 1);
        g_edges[p0] = (unsigned)c.x | ((unsigned)q.x << 16);
        g_edges[p1] = (unsigned)c.y | ((unsigned)q.y << 16);
        g_edges[p2] = (unsigned)c.z | ((unsigned)q.z << 16);
        g_edges[p3] = (unsigned)c.w | ((unsigned)q.w << 16);
    }
    const int e = (nvec << 2) + i;
    if (e < nnz) {
        const int row = __ldg(rowp + e);
        const int pos = atomicAdd(&g_cur[row], 1);
        g_edges[pos] = (unsigned)__ldg(colp + e) | ((unsigned)__ldg(relp + e) << 16);
    }
}

// ---------------------------------------------------------------------------
// K5: gather SpMM. Warp per row; uint4 broadcast edge loads (4 edges/load),
// 4 independent 512B gathers in flight. No atomics, coalesced store.
// ---------------------------------------------------------------------------
__device__ __forceinline__ void acc_edge(unsigned p, int lane,
                                         const float* __restrict__ inlayer,
                                         float4& a) {
    const int   col = (int)(p & 0xFFFFu);
    const float c   = g_coef[p >> 16];
    const float4 v  = __ldg(reinterpret_cast<const float4*>(
                                inlayer + (size_t)col * D) + lane);
    a.x += c * v.x; a.y += c * v.y; a.z += c * v.z; a.w += c * v.w;
}

__global__ void __launch_bounds__(256)
k_gather(const float* __restrict__ inlayer, float* __restrict__ out) {
    const int lane = threadIdx.x & 31;
    const int row  = (blockIdx.x * blockDim.x + threadIdx.x) >> 5;
    if (row >= N_NODES) return;

    const int s = __ldg(&g_offs[row]);
    const int e = __ldg(&g_offs[row + 1]);

    float4 a0 = make_float4(0.f, 0.f, 0.f, 0.f);
    float4 a1 = make_float4(0.f, 0.f, 0.f, 0.f);
    float4 a2 = make_float4(0.f, 0.f, 0.f, 0.f);
    float4 a3 = make_float4(0.f, 0.f, 0.f, 0.f);

    int i = s;
    while (i < e && (i & 3)) { acc_edge(__ldg(&g_edges[i]), lane, inlayer, a0); i++; }
    for (; i + 3 < e; i += 4) {
        const uint4 p = __ldg(reinterpret_cast<const uint4*>(g_edges + i));
        acc_edge(p.x, lane, inlayer, a0);
        acc_edge(p.y, lane, inlayer, a1);
        acc_edge(p.z, lane, inlayer, a2);
        acc_edge(p.w, lane, inlayer, a3);
    }
    for (; i < e; i++) acc_edge(__ldg(&g_edges[i]), lane, inlayer, a0);

    a0.x += a1.x + a2.x + a3.x;
    a0.y += a1.y + a2.y + a3.y;
    a0.z += a1.z + a2.z + a3.z;
    a0.w += a1.w + a2.w + a3.w;
    reinterpret_cast<float4*>(out + (size_t)row * D)[lane] = a0;
}

// ---------------------------------------------------------------------------
// kernel_launch
// Inputs: 0 inlayer [N,D] f32 | 1 dual [R,D] f32 | 2 conv_w [D] f32
//         3 conv_b [1] f32    | 4 edge_idx [2,NNZ] i32 | 5 edge_rel [NNZ] i32
// Output: [N, D] f32
// ---------------------------------------------------------------------------
extern "C" void kernel_launch(void* const* d_in, const int* in_sizes, int n_in,
                              void* d_out, int out_size) {
    const float* inlayer = (const float*)d_in[0];
    const float* dual    = (const float*)d_in[1];
    const float* conv_w  = (const float*)d_in[2];
    const float* conv_b  = (const float*)d_in[3];
    const int*   eidx    = (const int*)d_in[4];
    const int*   erel    = (const int*)d_in[5];
    float*       out     = (float*)d_out;

    const int nnz = in_sizes[5];
    const int* rowp = eidx;
    const int* colp = eidx + nnz;

    k_scores<<<(N_REL * 32 + 255) / 256, 256>>>(dual, conv_w, conv_b);
    k_hist_sum<<<592, 256>>>(rowp, erel, nnz);
    k_scan<<<SCAN_NB, SCAN_BLK>>>(nnz);
    k_reorder<<<(nnz / 4 + 255) / 256, 256>>>(rowp, colp, erel, nnz);
    k_gather<<<(N_NODES * 32 + 255) / 256, 256>>>(inlayer, out);
}